// round 5
// baseline (speedup 1.0000x reference)
#include <cuda_runtime.h>

// GraphConvolution: out = segment_sum(edge_val * (x@W)[edge_col] by edge_row) + b
// N=50000, E=800000, D_IN=D_OUT=96
// Strategy: dense GEMM; coarse row-bucketing (64 rows/bucket); one block per
// bucket accumulates a 64x96 tile in SMEM (smem atomics), single write + bias.

#define DIN  96
#define DOUT 96
#define MAXN 50000
#define MAXE 800000
#define RPB  64                      // rows per bucket
#define MAXB ((MAXN + RPB - 1) / RPB)

__device__ float g_support[(size_t)MAXN * DOUT];
__device__ int   g_bcnt[MAXB];       // edges per bucket
__device__ int   g_bstart[MAXB];     // segment start per bucket
__device__ int   g_bfill[MAXB];      // fill cursor
__device__ int2  g_edges[MAXE];      // (col | row_local<<17, val bits)
__device__ int   g_total;

// ---------------------------------------------------------------------------
__global__ void zero_kernel(int NB) {
    int i = blockIdx.x * blockDim.x + threadIdx.x;
    if (i < NB) g_bcnt[i] = 0;
    if (i == 0) g_total = 0;
}

__global__ void hist_kernel(const int* __restrict__ er, int E) {
    int e = blockIdx.x * blockDim.x + threadIdx.x;
    if (e < E) atomicAdd(&g_bcnt[__ldg(er + e) / RPB], 1);
}

// warp-scan segment allocation over NB buckets
__global__ void alloc_kernel(int NB) {
    int i = blockIdx.x * blockDim.x + threadIdx.x;
    int lane = threadIdx.x & 31;
    int c = (i < NB) ? g_bcnt[i] : 0;
    int v = c;
#pragma unroll
    for (int d = 1; d < 32; d <<= 1) {
        int t = __shfl_up_sync(0xffffffffu, v, d);
        if (lane >= d) v += t;
    }
    int wtot = __shfl_sync(0xffffffffu, v, 31);
    int base = 0;
    if (lane == 31) base = atomicAdd(&g_total, wtot);
    base = __shfl_sync(0xffffffffu, base, 31);
    if (i < NB) { g_bstart[i] = base + v - c; g_bfill[i] = base + v - c; }
}

__global__ void bucket_kernel(const int*   __restrict__ er,
                              const int*   __restrict__ ec,
                              const float* __restrict__ ev, int E) {
    int e = blockIdx.x * blockDim.x + threadIdx.x;
    if (e < E) {
        int r  = __ldg(er + e);
        int b  = r / RPB;
        int rl = r - b * RPB;                       // 0..63
        int p  = atomicAdd(&g_bfill[b], 1);
        g_edges[p] = make_int2(__ldg(ec + e) | (rl << 17),
                               __float_as_int(__ldg(ev + e)));
    }
}

// ---------------------------------------------------------------------------
// support = x @ W.   W staged in shared; each thread: 4 rows x 4 cols.
__global__ void __launch_bounds__(384)
gemm_kernel(const float* __restrict__ x,
            const float* __restrict__ w,
            float* __restrict__ sup, int N) {
    __shared__ float4 Ws[DIN][DOUT / 4];

    int tid = threadIdx.x;
    const float4* w4 = (const float4*)w;
#pragma unroll
    for (int i = tid; i < DIN * DOUT / 4; i += 384)
        Ws[i / (DOUT / 4)][i % (DOUT / 4)] = w4[i];
    __syncthreads();

    int c4 = tid % 24;
    int r0 = blockIdx.x * 64 + (tid / 24) * 4;

    const float4* xr[4];
    bool valid[4];
#pragma unroll
    for (int j = 0; j < 4; j++) {
        int row  = r0 + j;
        valid[j] = (row < N);
        int rowc = valid[j] ? row : (N - 1);
        xr[j] = (const float4*)(x + (size_t)rowc * DIN);
    }

    float4 acc[4];
#pragma unroll
    for (int j = 0; j < 4; j++) acc[j] = make_float4(0.f, 0.f, 0.f, 0.f);

#pragma unroll 4
    for (int kk = 0; kk < DIN / 4; kk++) {
        float4 xv[4];
#pragma unroll
        for (int j = 0; j < 4; j++) xv[j] = __ldg(xr[j] + kk);
#pragma unroll
        for (int t = 0; t < 4; t++) {
            float4 wv = Ws[kk * 4 + t][c4];
#pragma unroll
            for (int j = 0; j < 4; j++) {
                float xs = (t == 0) ? xv[j].x : (t == 1) ? xv[j].y
                                              : (t == 2) ? xv[j].z : xv[j].w;
                acc[j].x += xs * wv.x;
                acc[j].y += xs * wv.y;
                acc[j].z += xs * wv.z;
                acc[j].w += xs * wv.w;
            }
        }
    }

#pragma unroll
    for (int j = 0; j < 4; j++)
        if (valid[j])
            ((float4*)(sup + (size_t)(r0 + j) * DOUT))[c4] = acc[j];
}

// ---------------------------------------------------------------------------
// SpMM: one block per bucket. SMEM tile 64x96 f32 accum; smem atomics;
// single global write per output element (+ bias fused).
__global__ void __launch_bounds__(512)
spmm_kernel(const float* __restrict__ sup,
            const float* __restrict__ bias,
            float* __restrict__ out, int N) {
    __shared__ float acc[RPB * DOUT];            // 24.6 KB

    int b   = blockIdx.x;
    int tid = threadIdx.x;

#pragma unroll
    for (int i = tid; i < RPB * DOUT; i += 512) acc[i] = 0.f;
    __syncthreads();

    int base = g_bstart[b];
    int len  = g_bcnt[b];
    int work = len * 24;                          // (edge, c4) pairs

    for (int idx = tid; idx < work; idx += 512) {
        int e  = idx / 24;
        int c4 = idx - e * 24;
        int2 cv = __ldg((const int2*)g_edges + base + e);  // L1-cached
        int col = cv.x & 0x1FFFF;
        int rl  = cv.x >> 17;
        float v = __int_as_float(cv.y);

        float4 s = __ldg((const float4*)(sup + (size_t)col * DOUT) + c4);
        float* a = acc + rl * DOUT + c4 * 4;
        atomicAdd(a + 0, v * s.x);
        atomicAdd(a + 1, v * s.y);
        atomicAdd(a + 2, v * s.z);
        atomicAdd(a + 3, v * s.w);
    }
    __syncthreads();

    // write tile + bias; rows b*RPB .. b*RPB+63 (guard tail)
    int r0 = b * RPB;
#pragma unroll
    for (int i = tid; i < RPB * (DOUT / 4); i += 512) {
        int rl = i / (DOUT / 4);
        int c4 = i - rl * (DOUT / 4);
        int r  = r0 + rl;
        if (r < N) {
            float4 a = ((float4*)acc)[i];
            float4 bb = __ldg((const float4*)bias + c4);
            a.x += bb.x; a.y += bb.y; a.z += bb.z; a.w += bb.w;
            ((float4*)(out + (size_t)r * DOUT))[c4] = a;
        }
    }
}

// ---------------------------------------------------------------------------
extern "C" void kernel_launch(void* const* d_in, const int* in_sizes, int n_in,
                              void* d_out, int out_size) {
    const float* x      = (const float*)d_in[0];
    const int*   e_row  = (const int*)  d_in[1];
    const int*   e_col  = (const int*)  d_in[2];
    const float* e_val  = (const float*)d_in[3];
    const float* weight = (const float*)d_in[4];
    const float* bias   = (const float*)d_in[5];
    float*       out    = (float*)d_out;

    int N  = in_sizes[0] / DIN;
    int E  = in_sizes[1];
    int NB = (N + RPB - 1) / RPB;

    float* sup;
    cudaGetSymbolAddress((void**)&sup, g_support);

    // bucket build (cheap: coarse buckets)
    zero_kernel  <<<(NB + 255) / 256, 256>>>(NB);
    hist_kernel  <<<(E + 255) / 256, 256>>>(e_row, E);
    alloc_kernel <<<(NB + 255) / 256, 256>>>(NB);
    bucket_kernel<<<(E + 255) / 256, 256>>>(e_row, e_col, e_val, E);

    // dense GEMM
    gemm_kernel<<<(N + 63) / 64, 384>>>(x, weight, sup, N);

    // bucketed SpMM + bias
    spmm_kernel<<<NB, 512>>>(sup, bias, out, N);
}

// round 7
// speedup vs baseline: 3.6834x; 3.6834x over previous
#include <cuda_runtime.h>

// GraphConvolution: out = segment_sum(edge_val * (x@W)[edge_col] by edge_row) + b
// N=50000, E=800000, D_IN=D_OUT=96
// Strategy: dense GEMM -> vectorized per-row CSR build -> ILP-4 atomic-free SpMM.

#define DIN  96
#define DOUT 96
#define MAXN 50000
#define MAXE 800000

__device__ float g_support[(size_t)MAXN * DOUT];
__device__ int   g_cnt[MAXN];        // degree per row
__device__ int   g_rowstart[MAXN];   // segment start per row
__device__ int   g_fillpos[MAXN];    // fill cursor (consumed by pass 4)
__device__ int2  g_edges[MAXE];      // (col, val-bits) grouped by row
__device__ int   g_total;

// ---------------------------------------------------------------------------
__global__ void zero_kernel(int N) {
    int i = blockIdx.x * blockDim.x + threadIdx.x;
    if (i < N) g_cnt[i] = 0;
    if (i == 0) g_total = 0;
}

// histogram, 4 edges per thread (vector load + 4 independent ATOMGs)
__global__ void hist_kernel(const int* __restrict__ er, int E) {
    int t  = blockIdx.x * blockDim.x + threadIdx.x;
    int e0 = t * 4;
    if (e0 + 4 <= E) {
        int4 r = __ldg((const int4*)er + t);
        atomicAdd(&g_cnt[r.x], 1);
        atomicAdd(&g_cnt[r.y], 1);
        atomicAdd(&g_cnt[r.z], 1);
        atomicAdd(&g_cnt[r.w], 1);
    } else {
        for (int e = e0; e < E; e++) atomicAdd(&g_cnt[__ldg(er + e)], 1);
    }
}

// segment allocation: warp scan + one atomic per warp
__global__ void alloc_kernel(int N) {
    int i = blockIdx.x * blockDim.x + threadIdx.x;
    int lane = threadIdx.x & 31;
    int c = (i < N) ? g_cnt[i] : 0;
    int v = c;
#pragma unroll
    for (int d = 1; d < 32; d <<= 1) {
        int t = __shfl_up_sync(0xffffffffu, v, d);
        if (lane >= d) v += t;
    }
    int wtot = __shfl_sync(0xffffffffu, v, 31);
    int base = 0;
    if (lane == 31) base = atomicAdd(&g_total, wtot);
    base = __shfl_sync(0xffffffffu, base, 31);
    int start = base + v - c;
    if (i < N) { g_rowstart[i] = start; g_fillpos[i] = start; }
}

// bucket (col,val) into per-row segments, 4 edges per thread
__global__ void bucket_kernel(const int*   __restrict__ er,
                              const int*   __restrict__ ec,
                              const float* __restrict__ ev, int E) {
    int t  = blockIdx.x * blockDim.x + threadIdx.x;
    int e0 = t * 4;
    if (e0 + 4 <= E) {
        int4   r = __ldg((const int4*)er + t);
        int4   c = __ldg((const int4*)ec + t);
        float4 v = __ldg((const float4*)ev + t);
        int p0 = atomicAdd(&g_fillpos[r.x], 1);
        int p1 = atomicAdd(&g_fillpos[r.y], 1);
        int p2 = atomicAdd(&g_fillpos[r.z], 1);
        int p3 = atomicAdd(&g_fillpos[r.w], 1);
        g_edges[p0] = make_int2(c.x, __float_as_int(v.x));
        g_edges[p1] = make_int2(c.y, __float_as_int(v.y));
        g_edges[p2] = make_int2(c.z, __float_as_int(v.z));
        g_edges[p3] = make_int2(c.w, __float_as_int(v.w));
    } else {
        for (int e = e0; e < E; e++) {
            int r = __ldg(er + e);
            int p = atomicAdd(&g_fillpos[r], 1);
            g_edges[p] = make_int2(__ldg(ec + e), __float_as_int(__ldg(ev + e)));
        }
    }
}

// ---------------------------------------------------------------------------
// support = x @ W.   W staged in shared; each thread: 4 rows x 4 cols.
__global__ void __launch_bounds__(384)
gemm_kernel(const float* __restrict__ x,
            const float* __restrict__ w,
            float* __restrict__ sup, int N) {
    __shared__ float4 Ws[DIN][DOUT / 4];

    int tid = threadIdx.x;
    const float4* w4 = (const float4*)w;
#pragma unroll
    for (int i = tid; i < DIN * DOUT / 4; i += 384)
        Ws[i / (DOUT / 4)][i % (DOUT / 4)] = w4[i];
    __syncthreads();

    int c4 = tid % 24;
    int r0 = blockIdx.x * 64 + (tid / 24) * 4;

    const float4* xr[4];
    bool valid[4];
#pragma unroll
    for (int j = 0; j < 4; j++) {
        int row  = r0 + j;
        valid[j] = (row < N);
        int rowc = valid[j] ? row : (N - 1);
        xr[j] = (const float4*)(x + (size_t)rowc * DIN);
    }

    float4 acc[4];
#pragma unroll
    for (int j = 0; j < 4; j++) acc[j] = make_float4(0.f, 0.f, 0.f, 0.f);

#pragma unroll 4
    for (int kk = 0; kk < DIN / 4; kk++) {
        float4 xv[4];
#pragma unroll
        for (int j = 0; j < 4; j++) xv[j] = __ldg(xr[j] + kk);
#pragma unroll
        for (int t = 0; t < 4; t++) {
            float4 wv = Ws[kk * 4 + t][c4];
#pragma unroll
            for (int j = 0; j < 4; j++) {
                float xs = (t == 0) ? xv[j].x : (t == 1) ? xv[j].y
                                              : (t == 2) ? xv[j].z : xv[j].w;
                acc[j].x += xs * wv.x;
                acc[j].y += xs * wv.y;
                acc[j].z += xs * wv.z;
                acc[j].w += xs * wv.w;
            }
        }
    }

#pragma unroll
    for (int j = 0; j < 4; j++)
        if (valid[j])
            ((float4*)(sup + (size_t)(r0 + j) * DOUT))[c4] = acc[j];
}

// ---------------------------------------------------------------------------
// SpMM + bias: 24-thread group per row, register accumulation, 4-deep MLP.
__global__ void __launch_bounds__(384)
spmm_kernel(const float* __restrict__ sup,
            const float* __restrict__ b,
            float* __restrict__ out, int N) {
    int row = blockIdx.x * 16 + threadIdx.x / 24;
    int c4  = threadIdx.x % 24;
    if (row >= N) return;

    int s   = g_rowstart[row];
    int len = g_cnt[row];

    float4 acc = make_float4(0.f, 0.f, 0.f, 0.f);
    int j = 0;
    for (; j + 4 <= len; j += 4) {
        // 4 independent payload loads (coalesce within group), then
        // 4 independent float4 gathers -> deep MLP.
        int2 cv0 = __ldg((const int2*)g_edges + s + j + 0);
        int2 cv1 = __ldg((const int2*)g_edges + s + j + 1);
        int2 cv2 = __ldg((const int2*)g_edges + s + j + 2);
        int2 cv3 = __ldg((const int2*)g_edges + s + j + 3);
        float4 s0 = __ldg((const float4*)(sup + (size_t)cv0.x * DOUT) + c4);
        float4 s1 = __ldg((const float4*)(sup + (size_t)cv1.x * DOUT) + c4);
        float4 s2 = __ldg((const float4*)(sup + (size_t)cv2.x * DOUT) + c4);
        float4 s3 = __ldg((const float4*)(sup + (size_t)cv3.x * DOUT) + c4);
        float v0 = __int_as_float(cv0.y), v1 = __int_as_float(cv1.y);
        float v2 = __int_as_float(cv2.y), v3 = __int_as_float(cv3.y);
        acc.x += v0 * s0.x; acc.y += v0 * s0.y; acc.z += v0 * s0.z; acc.w += v0 * s0.w;
        acc.x += v1 * s1.x; acc.y += v1 * s1.y; acc.z += v1 * s1.z; acc.w += v1 * s1.w;
        acc.x += v2 * s2.x; acc.y += v2 * s2.y; acc.z += v2 * s2.z; acc.w += v2 * s2.w;
        acc.x += v3 * s3.x; acc.y += v3 * s3.y; acc.z += v3 * s3.z; acc.w += v3 * s3.w;
    }
    for (; j < len; j++) {
        int2 cv = __ldg((const int2*)g_edges + s + j);
        float4 sv = __ldg((const float4*)(sup + (size_t)cv.x * DOUT) + c4);
        float v = __int_as_float(cv.y);
        acc.x += v * sv.x; acc.y += v * sv.y; acc.z += v * sv.z; acc.w += v * sv.w;
    }

    float4 bb = __ldg((const float4*)b + c4);
    acc.x += bb.x; acc.y += bb.y; acc.z += bb.z; acc.w += bb.w;
    ((float4*)(out + (size_t)row * DOUT))[c4] = acc;
}

// ---------------------------------------------------------------------------
extern "C" void kernel_launch(void* const* d_in, const int* in_sizes, int n_in,
                              void* d_out, int out_size) {
    const float* x      = (const float*)d_in[0];
    const int*   e_row  = (const int*)  d_in[1];
    const int*   e_col  = (const int*)  d_in[2];
    const float* e_val  = (const float*)d_in[3];
    const float* weight = (const float*)d_in[4];
    const float* bias   = (const float*)d_in[5];
    float*       out    = (float*)d_out;

    int N = in_sizes[0] / DIN;
    int E = in_sizes[1];

    float* sup;
    cudaGetSymbolAddress((void**)&sup, g_support);

    int e4 = (E + 3) / 4;   // threads for 4-edge-per-thread kernels

    // CSR build (vectorized)
    zero_kernel  <<<(N + 255) / 256, 256>>>(N);
    hist_kernel  <<<(e4 + 255) / 256, 256>>>(e_row, E);
    alloc_kernel <<<(N + 255) / 256, 256>>>(N);
    bucket_kernel<<<(e4 + 255) / 256, 256>>>(e_row, e_col, e_val, E);

    // dense GEMM
    gemm_kernel<<<(N + 63) / 64, 384>>>(x, weight, sup, N);

    // atomic-free SpMM + bias
    spmm_kernel<<<(N + 15) / 16, 384>>>(sup, bias, out, N);
}

// round 9
// speedup vs baseline: 4.1185x; 1.1181x over previous
#include <cuda_runtime.h>

// GraphConvolution: out = segment_sum(edge_val * (x@W)[edge_col] by edge_row) + b
// N=50000, E=800000, D_IN=D_OUT=96
// Strategy: [CSR build || dense GEMM] fork-join inside the captured graph,
// then ILP-4 atomic-free SpMM (+bias fused).

#define DIN  96
#define DOUT 96
#define MAXN 50000
#define MAXE 800000

__device__ float g_support[(size_t)MAXN * DOUT];
__device__ int   g_cnt[MAXN];        // degree per row
__device__ int   g_rowstart[MAXN];   // segment start per row
__device__ int   g_fillpos[MAXN];    // fill cursor (consumed by bucket pass)
__device__ int2  g_edges[MAXE];      // (col, val-bits) grouped by row
__device__ int   g_total;

// ---------------------------------------------------------------------------
__global__ void zero_kernel(int N) {
    int i = blockIdx.x * blockDim.x + threadIdx.x;
    if (i < N) g_cnt[i] = 0;
    if (i == 0) g_total = 0;
}

// histogram, 8 edges per thread (2x int4 loads + 8 independent no-return REDGs)
__global__ void hist_kernel(const int* __restrict__ er, int E) {
    int t  = blockIdx.x * blockDim.x + threadIdx.x;
    int e0 = t * 8;
    if (e0 + 8 <= E) {
        int4 a = __ldg((const int4*)er + t * 2);
        int4 b = __ldg((const int4*)er + t * 2 + 1);
        atomicAdd(&g_cnt[a.x], 1); atomicAdd(&g_cnt[a.y], 1);
        atomicAdd(&g_cnt[a.z], 1); atomicAdd(&g_cnt[a.w], 1);
        atomicAdd(&g_cnt[b.x], 1); atomicAdd(&g_cnt[b.y], 1);
        atomicAdd(&g_cnt[b.z], 1); atomicAdd(&g_cnt[b.w], 1);
    } else {
        for (int e = e0; e < E; e++) atomicAdd(&g_cnt[__ldg(er + e)], 1);
    }
}

// segment allocation: warp scan + one atomic per warp
__global__ void alloc_kernel(int N) {
    int i = blockIdx.x * blockDim.x + threadIdx.x;
    int lane = threadIdx.x & 31;
    int c = (i < N) ? g_cnt[i] : 0;
    int v = c;
#pragma unroll
    for (int d = 1; d < 32; d <<= 1) {
        int t = __shfl_up_sync(0xffffffffu, v, d);
        if (lane >= d) v += t;
    }
    int wtot = __shfl_sync(0xffffffffu, v, 31);
    int base = 0;
    if (lane == 31) base = atomicAdd(&g_total, wtot);
    base = __shfl_sync(0xffffffffu, base, 31);
    int start = base + v - c;
    if (i < N) { g_rowstart[i] = start; g_fillpos[i] = start; }
}

// bucket (col,val) into per-row segments, 8 edges per thread (MLP=8 atomics)
__global__ void bucket_kernel(const int*   __restrict__ er,
                              const int*   __restrict__ ec,
                              const float* __restrict__ ev, int E) {
    int t  = blockIdx.x * blockDim.x + threadIdx.x;
    int e0 = t * 8;
    if (e0 + 8 <= E) {
        int4   r0 = __ldg((const int4*)er + t * 2);
        int4   r1 = __ldg((const int4*)er + t * 2 + 1);
        int4   c0 = __ldg((const int4*)ec + t * 2);
        int4   c1 = __ldg((const int4*)ec + t * 2 + 1);
        float4 v0 = __ldg((const float4*)ev + t * 2);
        float4 v1 = __ldg((const float4*)ev + t * 2 + 1);
        int p0 = atomicAdd(&g_fillpos[r0.x], 1);
        int p1 = atomicAdd(&g_fillpos[r0.y], 1);
        int p2 = atomicAdd(&g_fillpos[r0.z], 1);
        int p3 = atomicAdd(&g_fillpos[r0.w], 1);
        int p4 = atomicAdd(&g_fillpos[r1.x], 1);
        int p5 = atomicAdd(&g_fillpos[r1.y], 1);
        int p6 = atomicAdd(&g_fillpos[r1.z], 1);
        int p7 = atomicAdd(&g_fillpos[r1.w], 1);
        g_edges[p0] = make_int2(c0.x, __float_as_int(v0.x));
        g_edges[p1] = make_int2(c0.y, __float_as_int(v0.y));
        g_edges[p2] = make_int2(c0.z, __float_as_int(v0.z));
        g_edges[p3] = make_int2(c0.w, __float_as_int(v0.w));
        g_edges[p4] = make_int2(c1.x, __float_as_int(v1.x));
        g_edges[p5] = make_int2(c1.y, __float_as_int(v1.y));
        g_edges[p6] = make_int2(c1.z, __float_as_int(v1.z));
        g_edges[p7] = make_int2(c1.w, __float_as_int(v1.w));
    } else {
        for (int e = e0; e < E; e++) {
            int r = __ldg(er + e);
            int p = atomicAdd(&g_fillpos[r], 1);
            g_edges[p] = make_int2(__ldg(ec + e), __float_as_int(__ldg(ev + e)));
        }
    }
}

// ---------------------------------------------------------------------------
// support = x @ W.   W staged in shared; each thread: 4 rows x 4 cols.
__global__ void __launch_bounds__(384)
gemm_kernel(const float* __restrict__ x,
            const float* __restrict__ w,
            float* __restrict__ sup, int N) {
    __shared__ float4 Ws[DIN][DOUT / 4];

    int tid = threadIdx.x;
    const float4* w4 = (const float4*)w;
#pragma unroll
    for (int i = tid; i < DIN * DOUT / 4; i += 384)
        Ws[i / (DOUT / 4)][i % (DOUT / 4)] = w4[i];
    __syncthreads();

    int c4 = tid % 24;
    int r0 = blockIdx.x * 64 + (tid / 24) * 4;

    const float4* xr[4];
    bool valid[4];
#pragma unroll
    for (int j = 0; j < 4; j++) {
        int row  = r0 + j;
        valid[j] = (row < N);
        int rowc = valid[j] ? row : (N - 1);
        xr[j] = (const float4*)(x + (size_t)rowc * DIN);
    }

    float4 acc[4];
#pragma unroll
    for (int j = 0; j < 4; j++) acc[j] = make_float4(0.f, 0.f, 0.f, 0.f);

#pragma unroll 4
    for (int kk = 0; kk < DIN / 4; kk++) {
        float4 xv[4];
#pragma unroll
        for (int j = 0; j < 4; j++) xv[j] = __ldg(xr[j] + kk);
#pragma unroll
        for (int t = 0; t < 4; t++) {
            float4 wv = Ws[kk * 4 + t][c4];
#pragma unroll
            for (int j = 0; j < 4; j++) {
                float xs = (t == 0) ? xv[j].x : (t == 1) ? xv[j].y
                                              : (t == 2) ? xv[j].z : xv[j].w;
                acc[j].x += xs * wv.x;
                acc[j].y += xs * wv.y;
                acc[j].z += xs * wv.z;
                acc[j].w += xs * wv.w;
            }
        }
    }

#pragma unroll
    for (int j = 0; j < 4; j++)
        if (valid[j])
            ((float4*)(sup + (size_t)(r0 + j) * DOUT))[c4] = acc[j];
}

// ---------------------------------------------------------------------------
// SpMM + bias: 24-thread group per row, register accumulation, 4-deep MLP.
__global__ void __launch_bounds__(384)
spmm_kernel(const float* __restrict__ sup,
            const float* __restrict__ b,
            float* __restrict__ out, int N) {
    int row = blockIdx.x * 16 + threadIdx.x / 24;
    int c4  = threadIdx.x % 24;
    if (row >= N) return;

    int s   = g_rowstart[row];
    int len = g_cnt[row];

    float4 acc = make_float4(0.f, 0.f, 0.f, 0.f);
    int j = 0;
    for (; j + 4 <= len; j += 4) {
        int2 cv0 = __ldg((const int2*)g_edges + s + j + 0);
        int2 cv1 = __ldg((const int2*)g_edges + s + j + 1);
        int2 cv2 = __ldg((const int2*)g_edges + s + j + 2);
        int2 cv3 = __ldg((const int2*)g_edges + s + j + 3);
        float4 s0 = __ldg((const float4*)(sup + (size_t)cv0.x * DOUT) + c4);
        float4 s1 = __ldg((const float4*)(sup + (size_t)cv1.x * DOUT) + c4);
        float4 s2 = __ldg((const float4*)(sup + (size_t)cv2.x * DOUT) + c4);
        float4 s3 = __ldg((const float4*)(sup + (size_t)cv3.x * DOUT) + c4);
        float v0 = __int_as_float(cv0.y), v1 = __int_as_float(cv1.y);
        float v2 = __int_as_float(cv2.y), v3 = __int_as_float(cv3.y);
        acc.x += v0 * s0.x; acc.y += v0 * s0.y; acc.z += v0 * s0.z; acc.w += v0 * s0.w;
        acc.x += v1 * s1.x; acc.y += v1 * s1.y; acc.z += v1 * s1.z; acc.w += v1 * s1.w;
        acc.x += v2 * s2.x; acc.y += v2 * s2.y; acc.z += v2 * s2.z; acc.w += v2 * s2.w;
        acc.x += v3 * s3.x; acc.y += v3 * s3.y; acc.z += v3 * s3.z; acc.w += v3 * s3.w;
    }
    for (; j < len; j++) {
        int2 cv = __ldg((const int2*)g_edges + s + j);
        float4 sv = __ldg((const float4*)(sup + (size_t)cv.x * DOUT) + c4);
        float v = __int_as_float(cv.y);
        acc.x += v * sv.x; acc.y += v * sv.y; acc.z += v * sv.z; acc.w += v * sv.w;
    }

    float4 bb = __ldg((const float4*)b + c4);
    acc.x += bb.x; acc.y += bb.y; acc.z += bb.z; acc.w += bb.w;
    ((float4*)(out + (size_t)row * DOUT))[c4] = acc;
}

// ---------------------------------------------------------------------------
extern "C" void kernel_launch(void* const* d_in, const int* in_sizes, int n_in,
                              void* d_out, int out_size) {
    const float* x      = (const float*)d_in[0];
    const int*   e_row  = (const int*)  d_in[1];
    const int*   e_col  = (const int*)  d_in[2];
    const float* e_val  = (const float*)d_in[3];
    const float* weight = (const float*)d_in[4];
    const float* bias   = (const float*)d_in[5];
    float*       out    = (float*)d_out;

    int N = in_sizes[0] / DIN;
    int E = in_sizes[1];

    float* sup;
    cudaGetSymbolAddress((void**)&sup, g_support);

    // One-time creation of side stream + events. This happens on the first
    // call (the eager correctness run), never while a capture is active.
    static cudaStream_t s_build = nullptr;
    static cudaEvent_t  ev_fork = nullptr, ev_build = nullptr;
    static bool init_done = false;
    if (!init_done) {
        init_done = true;
        cudaStreamCreateWithFlags(&s_build, cudaStreamNonBlocking);
        cudaEventCreateWithFlags(&ev_fork,  cudaEventDisableTiming);
        cudaEventCreateWithFlags(&ev_build, cudaEventDisableTiming);
    }

    int e8 = (E + 7) / 8;

    if (s_build && ev_fork && ev_build) {
        // ---- fork: CSR build on side stream, GEMM on main stream ----------
        cudaEventRecord(ev_fork, 0);
        cudaStreamWaitEvent(s_build, ev_fork, 0);

        zero_kernel  <<<(N + 255) / 256, 256, 0, s_build>>>(N);
        hist_kernel  <<<(e8 + 255) / 256, 256, 0, s_build>>>(e_row, E);
        alloc_kernel <<<(N + 255) / 256, 256, 0, s_build>>>(N);
        bucket_kernel<<<(e8 + 255) / 256, 256, 0, s_build>>>(e_row, e_col, e_val, E);
        cudaEventRecord(ev_build, s_build);

        gemm_kernel<<<(N + 63) / 64, 384>>>(x, weight, sup, N);

        // ---- join: side stream fully merged back before SpMM --------------
        cudaStreamWaitEvent(0, ev_build, 0);
    } else {
        // Fallback: fully serial on the main stream.
        zero_kernel  <<<(N + 255) / 256, 256>>>(N);
        hist_kernel  <<<(e8 + 255) / 256, 256>>>(e_row, E);
        alloc_kernel <<<(N + 255) / 256, 256>>>(N);
        bucket_kernel<<<(e8 + 255) / 256, 256>>>(e_row, e_col, e_val, E);
        gemm_kernel  <<<(N + 63) / 64, 384>>>(x, weight, sup, N);
    }

    spmm_kernel<<<(N + 15) / 16, 384>>>(sup, bias, out, N);
}

// round 10
// speedup vs baseline: 4.4836x; 1.0886x over previous
#include <cuda_runtime.h>
#include <cuda_fp16.h>

// GraphConvolution: out = segment_sum(edge_val * (x@W)[edge_col] by edge_row) + b
// N=50000, E=800000, D_IN=D_OUT=96
// Strategy: [CSR build || dense GEMM] fork-join in the captured graph; support
// stored fp16 (halves SpMM gather traffic); ILP-4 atomic-free SpMM (+bias),
// fp32 accumulation and fp32 output.

#define DIN  96
#define DOUT 96
#define MAXN 50000
#define MAXE 800000

__device__ __half g_support[(size_t)MAXN * DOUT];   // fp16 support
__device__ int    g_cnt[MAXN];
__device__ int    g_rowstart[MAXN];
__device__ int    g_fillpos[MAXN];
__device__ int2   g_edges[MAXE];
__device__ int    g_total;

// ---------------------------------------------------------------------------
__global__ void zero_kernel(int N) {
    int i = blockIdx.x * blockDim.x + threadIdx.x;
    if (i < N) g_cnt[i] = 0;
    if (i == 0) g_total = 0;
}

__global__ void hist_kernel(const int* __restrict__ er, int E) {
    int t  = blockIdx.x * blockDim.x + threadIdx.x;
    int e0 = t * 8;
    if (e0 + 8 <= E) {
        int4 a = __ldg((const int4*)er + t * 2);
        int4 b = __ldg((const int4*)er + t * 2 + 1);
        atomicAdd(&g_cnt[a.x], 1); atomicAdd(&g_cnt[a.y], 1);
        atomicAdd(&g_cnt[a.z], 1); atomicAdd(&g_cnt[a.w], 1);
        atomicAdd(&g_cnt[b.x], 1); atomicAdd(&g_cnt[b.y], 1);
        atomicAdd(&g_cnt[b.z], 1); atomicAdd(&g_cnt[b.w], 1);
    } else {
        for (int e = e0; e < E; e++) atomicAdd(&g_cnt[__ldg(er + e)], 1);
    }
}

__global__ void alloc_kernel(int N) {
    int i = blockIdx.x * blockDim.x + threadIdx.x;
    int lane = threadIdx.x & 31;
    int c = (i < N) ? g_cnt[i] : 0;
    int v = c;
#pragma unroll
    for (int d = 1; d < 32; d <<= 1) {
        int t = __shfl_up_sync(0xffffffffu, v, d);
        if (lane >= d) v += t;
    }
    int wtot = __shfl_sync(0xffffffffu, v, 31);
    int base = 0;
    if (lane == 31) base = atomicAdd(&g_total, wtot);
    base = __shfl_sync(0xffffffffu, base, 31);
    int start = base + v - c;
    if (i < N) { g_rowstart[i] = start; g_fillpos[i] = start; }
}

__global__ void bucket_kernel(const int*   __restrict__ er,
                              const int*   __restrict__ ec,
                              const float* __restrict__ ev, int E) {
    int t  = blockIdx.x * blockDim.x + threadIdx.x;
    int e0 = t * 8;
    if (e0 + 8 <= E) {
        int4   r0 = __ldg((const int4*)er + t * 2);
        int4   r1 = __ldg((const int4*)er + t * 2 + 1);
        int4   c0 = __ldg((const int4*)ec + t * 2);
        int4   c1 = __ldg((const int4*)ec + t * 2 + 1);
        float4 v0 = __ldg((const float4*)ev + t * 2);
        float4 v1 = __ldg((const float4*)ev + t * 2 + 1);
        int p0 = atomicAdd(&g_fillpos[r0.x], 1);
        int p1 = atomicAdd(&g_fillpos[r0.y], 1);
        int p2 = atomicAdd(&g_fillpos[r0.z], 1);
        int p3 = atomicAdd(&g_fillpos[r0.w], 1);
        int p4 = atomicAdd(&g_fillpos[r1.x], 1);
        int p5 = atomicAdd(&g_fillpos[r1.y], 1);
        int p6 = atomicAdd(&g_fillpos[r1.z], 1);
        int p7 = atomicAdd(&g_fillpos[r1.w], 1);
        g_edges[p0] = make_int2(c0.x, __float_as_int(v0.x));
        g_edges[p1] = make_int2(c0.y, __float_as_int(v0.y));
        g_edges[p2] = make_int2(c0.z, __float_as_int(v0.z));
        g_edges[p3] = make_int2(c0.w, __float_as_int(v0.w));
        g_edges[p4] = make_int2(c1.x, __float_as_int(v1.x));
        g_edges[p5] = make_int2(c1.y, __float_as_int(v1.y));
        g_edges[p6] = make_int2(c1.z, __float_as_int(v1.z));
        g_edges[p7] = make_int2(c1.w, __float_as_int(v1.w));
    } else {
        for (int e = e0; e < E; e++) {
            int r = __ldg(er + e);
            int p = atomicAdd(&g_fillpos[r], 1);
            g_edges[p] = make_int2(__ldg(ec + e), __float_as_int(__ldg(ev + e)));
        }
    }
}

// ---------------------------------------------------------------------------
// support = fp16(x @ W).  fp32 accumulation, fp16 store (8B per thread-row).
__global__ void __launch_bounds__(384)
gemm_kernel(const float* __restrict__ x,
            const float* __restrict__ w,
            __half* __restrict__ sup, int N) {
    __shared__ float4 Ws[DIN][DOUT / 4];

    int tid = threadIdx.x;
    const float4* w4 = (const float4*)w;
#pragma unroll
    for (int i = tid; i < DIN * DOUT / 4; i += 384)
        Ws[i / (DOUT / 4)][i % (DOUT / 4)] = w4[i];
    __syncthreads();

    int c4 = tid % 24;
    int r0 = blockIdx.x * 64 + (tid / 24) * 4;

    const float4* xr[4];
    bool valid[4];
#pragma unroll
    for (int j = 0; j < 4; j++) {
        int row  = r0 + j;
        valid[j] = (row < N);
        int rowc = valid[j] ? row : (N - 1);
        xr[j] = (const float4*)(x + (size_t)rowc * DIN);
    }

    float4 acc[4];
#pragma unroll
    for (int j = 0; j < 4; j++) acc[j] = make_float4(0.f, 0.f, 0.f, 0.f);

#pragma unroll 4
    for (int kk = 0; kk < DIN / 4; kk++) {
        float4 xv[4];
#pragma unroll
        for (int j = 0; j < 4; j++) xv[j] = __ldg(xr[j] + kk);
#pragma unroll
        for (int t = 0; t < 4; t++) {
            float4 wv = Ws[kk * 4 + t][c4];
#pragma unroll
            for (int j = 0; j < 4; j++) {
                float xs = (t == 0) ? xv[j].x : (t == 1) ? xv[j].y
                                              : (t == 2) ? xv[j].z : xv[j].w;
                acc[j].x += xs * wv.x;
                acc[j].y += xs * wv.y;
                acc[j].z += xs * wv.z;
                acc[j].w += xs * wv.w;
            }
        }
    }

#pragma unroll
    for (int j = 0; j < 4; j++) {
        if (valid[j]) {
            __half2 p0 = __floats2half2_rn(acc[j].x, acc[j].y);
            __half2 p1 = __floats2half2_rn(acc[j].z, acc[j].w);
            uint2 u;
            u.x = *(const unsigned int*)&p0;
            u.y = *(const unsigned int*)&p1;
            ((uint2*)(sup + (size_t)(r0 + j) * DOUT))[c4] = u;
        }
    }
}

// ---------------------------------------------------------------------------
// SpMM + bias: 24-thread group per row; fp16 gather (8B/thread), fp32 accum.
__global__ void __launch_bounds__(384)
spmm_kernel(const __half* __restrict__ sup,
            const float* __restrict__ b,
            float* __restrict__ out, int N) {
    int row = blockIdx.x * 16 + threadIdx.x / 24;
    int c4  = threadIdx.x % 24;
    if (row >= N) return;

    int s   = g_rowstart[row];
    int len = g_cnt[row];

    float4 acc = make_float4(0.f, 0.f, 0.f, 0.f);
    int j = 0;
    for (; j + 4 <= len; j += 4) {
        int2 cv0 = __ldg((const int2*)g_edges + s + j + 0);
        int2 cv1 = __ldg((const int2*)g_edges + s + j + 1);
        int2 cv2 = __ldg((const int2*)g_edges + s + j + 2);
        int2 cv3 = __ldg((const int2*)g_edges + s + j + 3);
        uint2 u0 = __ldg((const uint2*)(sup + (size_t)cv0.x * DOUT) + c4);
        uint2 u1 = __ldg((const uint2*)(sup + (size_t)cv1.x * DOUT) + c4);
        uint2 u2 = __ldg((const uint2*)(sup + (size_t)cv2.x * DOUT) + c4);
        uint2 u3 = __ldg((const uint2*)(sup + (size_t)cv3.x * DOUT) + c4);
        float v0 = __int_as_float(cv0.y), v1 = __int_as_float(cv1.y);
        float v2 = __int_as_float(cv2.y), v3 = __int_as_float(cv3.y);

        float2 a0 = __half22float2(*(const __half2*)&u0.x);
        float2 b0 = __half22float2(*(const __half2*)&u0.y);
        float2 a1 = __half22float2(*(const __half2*)&u1.x);
        float2 b1 = __half22float2(*(const __half2*)&u1.y);
        float2 a2 = __half22float2(*(const __half2*)&u2.x);
        float2 b2 = __half22float2(*(const __half2*)&u2.y);
        float2 a3 = __half22float2(*(const __half2*)&u3.x);
        float2 b3 = __half22float2(*(const __half2*)&u3.y);

        acc.x += v0 * a0.x; acc.y += v0 * a0.y; acc.z += v0 * b0.x; acc.w += v0 * b0.y;
        acc.x += v1 * a1.x; acc.y += v1 * a1.y; acc.z += v1 * b1.x; acc.w += v1 * b1.y;
        acc.x += v2 * a2.x; acc.y += v2 * a2.y; acc.z += v2 * b2.x; acc.w += v2 * b2.y;
        acc.x += v3 * a3.x; acc.y += v3 * a3.y; acc.z += v3 * b3.x; acc.w += v3 * b3.y;
    }
    for (; j < len; j++) {
        int2 cv = __ldg((const int2*)g_edges + s + j);
        uint2 u = __ldg((const uint2*)(sup + (size_t)cv.x * DOUT) + c4);
        float v = __int_as_float(cv.y);
        float2 a = __half22float2(*(const __half2*)&u.x);
        float2 bq = __half22float2(*(const __half2*)&u.y);
        acc.x += v * a.x; acc.y += v * a.y; acc.z += v * bq.x; acc.w += v * bq.y;
    }

    float4 bb = __ldg((const float4*)b + c4);
    acc.x += bb.x; acc.y += bb.y; acc.z += bb.z; acc.w += bb.w;
    ((float4*)(out + (size_t)row * DOUT))[c4] = acc;
}

// ---------------------------------------------------------------------------
extern "C" void kernel_launch(void* const* d_in, const int* in_sizes, int n_in,
                              void* d_out, int out_size) {
    const float* x      = (const float*)d_in[0];
    const int*   e_row  = (const int*)  d_in[1];
    const int*   e_col  = (const int*)  d_in[2];
    const float* e_val  = (const float*)d_in[3];
    const float* weight = (const float*)d_in[4];
    const float* bias   = (const float*)d_in[5];
    float*       out    = (float*)d_out;

    int N = in_sizes[0] / DIN;
    int E = in_sizes[1];

    __half* sup;
    cudaGetSymbolAddress((void**)&sup, g_support);

    static cudaStream_t s_build = nullptr;
    static cudaEvent_t  ev_fork = nullptr, ev_build = nullptr;
    static bool init_done = false;
    if (!init_done) {
        init_done = true;
        cudaStreamCreateWithFlags(&s_build, cudaStreamNonBlocking);
        cudaEventCreateWithFlags(&ev_fork,  cudaEventDisableTiming);
        cudaEventCreateWithFlags(&ev_build, cudaEventDisableTiming);
    }

    int e8 = (E + 7) / 8;

    if (s_build && ev_fork && ev_build) {
        cudaEventRecord(ev_fork, 0);
        cudaStreamWaitEvent(s_build, ev_fork, 0);

        zero_kernel  <<<(N + 255) / 256, 256, 0, s_build>>>(N);
        hist_kernel  <<<(e8 + 255) / 256, 256, 0, s_build>>>(e_row, E);
        alloc_kernel <<<(N + 255) / 256, 256, 0, s_build>>>(N);
        bucket_kernel<<<(e8 + 255) / 256, 256, 0, s_build>>>(e_row, e_col, e_val, E);
        cudaEventRecord(ev_build, s_build);

        gemm_kernel<<<(N + 63) / 64, 384>>>(x, weight, sup, N);

        cudaStreamWaitEvent(0, ev_build, 0);
    } else {
        zero_kernel  <<<(N + 255) / 256, 256>>>(N);
        hist_kernel  <<<(e8 + 255) / 256, 256>>>(e_row, E);
        alloc_kernel <<<(N + 255) / 256, 256>>>(N);
        bucket_kernel<<<(e8 + 255) / 256, 256>>>(e_row, e_col, e_val, E);
        gemm_kernel  <<<(N + 63) / 64, 384>>>(x, weight, sup, N);
    }

    spmm_kernel<<<(N + 15) / 16, 384>>>(sup, bias, out, N);
}